// round 7
// baseline (speedup 1.0000x reference)
#include <cuda_runtime.h>
#include <cuda_fp16.h>

#define NN   100000
#define NE   1600000
#define HID  128
#define NOUT 64
#define FULLM 0xffffffffu

// ---------------- scratch (device globals; no allocations allowed) -----------
__device__ int   g_cnt[NN];
__device__ int   g_rowptr[NN + 1];
__device__ int   g_cursor[NN];
__device__ float g_dis[NN];
__device__ uint2 g_edge[NE];              // {col, norm bits}
__device__ uint2 g_xh[(size_t)NN * 32];   // x in half  (128 half = 32 uint2)
__device__ uint2 g_hA[(size_t)NN * 32];   // h1 in half
__device__ uint2 g_hB[(size_t)NN * 32];   // h2 in half

__device__ __forceinline__ int clampN(int v) {
    v = v < 0 ? 0 : v;
    return v >= NN ? NN - 1 : v;
}

__device__ __forceinline__ uint2 pack4h(float a, float b, float c, float d) {
    __half2 h0 = __floats2half2_rn(a, b);
    __half2 h1 = __floats2half2_rn(c, d);
    uint2 r;
    r.x = *reinterpret_cast<unsigned*>(&h0);
    r.y = *reinterpret_cast<unsigned*>(&h1);
    return r;
}

__device__ __forceinline__ void unpack4h(uint2 v, float& a, float& b, float& c, float& d) {
    __half2 h0 = *reinterpret_cast<__half2*>(&v.x);
    __half2 h1 = *reinterpret_cast<__half2*>(&v.y);
    float2 f0 = __half22float2(h0);
    float2 f1 = __half22float2(h1);
    a = f0.x; b = f0.y; c = f1.x; d = f1.y;
}

// ---------------- x -> half conversion (+ zero counts, fused) ----------------
__global__ void k_x2h(const float4* __restrict__ x4) {
    int i = blockIdx.x * blockDim.x + threadIdx.x;
    if (i < NN) g_cnt[i] = 0;
    if (i < NN * 32) {
        float4 v = x4[i];
        g_xh[i] = pack4h(v.x, v.y, v.z, v.w);
    }
}

// ---------------- CSR build ---------------------------------------------------
__global__ void k_count(const int* __restrict__ ei) {
    int e = blockIdx.x * blockDim.x + threadIdx.x;
    if (e < NE) atomicAdd(&g_cnt[clampN(ei[e])], 1);
}

// single-block exclusive scan of g_cnt -> g_rowptr
__global__ void k_scan() {
    __shared__ int s_warp[32];
    __shared__ int s_carry;
    const int tid = threadIdx.x, lane = tid & 31, wid = tid >> 5;
    if (tid == 0) { s_carry = 0; g_rowptr[0] = 0; }
    __syncthreads();
    for (int base = 0; base < NN; base += 4096) {
        int idx = base + tid * 4;
        int v0 = 0, v1 = 0, v2 = 0, v3 = 0;
        if (idx + 3 < NN) {
            int4 q = *(const int4*)&g_cnt[idx];
            v0 = q.x; v1 = q.y; v2 = q.z; v3 = q.w;
        } else {
            if (idx + 0 < NN) v0 = g_cnt[idx + 0];
            if (idx + 1 < NN) v1 = g_cnt[idx + 1];
            if (idx + 2 < NN) v2 = g_cnt[idx + 2];
            if (idx + 3 < NN) v3 = g_cnt[idx + 3];
        }
        int s = v0 + v1 + v2 + v3;
        int x = s;
        #pragma unroll
        for (int d = 1; d < 32; d <<= 1) {
            int t = __shfl_up_sync(FULLM, x, d);
            if (lane >= d) x += t;
        }
        if (lane == 31) s_warp[wid] = x;
        __syncthreads();
        if (wid == 0) {
            int y = s_warp[lane];
            #pragma unroll
            for (int d = 1; d < 32; d <<= 1) {
                int t = __shfl_up_sync(FULLM, y, d);
                if (lane >= d) y += t;
            }
            s_warp[lane] = y;
        }
        __syncthreads();
        int incl = x + (wid > 0 ? s_warp[wid - 1] : 0) + s_carry;
        int p = incl - s;
        if (idx + 0 < NN) { p += v0; g_rowptr[idx + 1] = p; }
        if (idx + 1 < NN) { p += v1; g_rowptr[idx + 2] = p; }
        if (idx + 2 < NN) { p += v2; g_rowptr[idx + 3] = p; }
        if (idx + 3 < NN) { p += v3; g_rowptr[idx + 4] = p; }
        __syncthreads();
        if (tid == blockDim.x - 1) s_carry = incl;
        __syncthreads();
    }
}

__global__ void k_prep() {
    int i = blockIdx.x * blockDim.x + threadIdx.x;
    if (i < NN) {
        g_dis[i]    = rsqrtf(fmaxf((float)g_cnt[i], 1.0f));
        g_cursor[i] = g_rowptr[i];
    }
}

__global__ void k_scatter(const int* __restrict__ ei) {
    int e = blockIdx.x * blockDim.x + threadIdx.x;
    if (e < NE) {
        int r = clampN(ei[e]);
        int c = clampN(ei[NE + e]);
        int pos = atomicAdd(&g_cursor[r], 1);
        float nrm = g_dis[r] * g_dis[c];
        g_edge[pos] = make_uint2((unsigned)c, __float_as_uint(nrm));
    }
}

// ---------------- gather core (warp computes one node's aggregation) ---------
__device__ __forceinline__ void gather_node(const uint2* __restrict__ src,
                                            int beg, int end, int lane,
                                            float& ax, float& ay, float& az, float& aw) {
    ax = 0.f; ay = 0.f; az = 0.f; aw = 0.f;
    for (int e0 = beg; e0 < end; e0 += 32) {
        int e = e0 + lane;
        int   cc = 0;
        float ww = 0.f;
        if (e < end) { uint2 ed = g_edge[e]; cc = (int)ed.x; ww = __uint_as_float(ed.y); }
        int m = end - e0; if (m > 32) m = 32;
        int j = 0;
        for (; j + 8 <= m; j += 8) {
            int   c0 = __shfl_sync(FULLM, cc, j + 0);
            int   c1 = __shfl_sync(FULLM, cc, j + 1);
            int   c2 = __shfl_sync(FULLM, cc, j + 2);
            int   c3 = __shfl_sync(FULLM, cc, j + 3);
            int   c4 = __shfl_sync(FULLM, cc, j + 4);
            int   c5 = __shfl_sync(FULLM, cc, j + 5);
            int   c6 = __shfl_sync(FULLM, cc, j + 6);
            int   c7 = __shfl_sync(FULLM, cc, j + 7);
            float w0 = __shfl_sync(FULLM, ww, j + 0);
            float w1 = __shfl_sync(FULLM, ww, j + 1);
            float w2 = __shfl_sync(FULLM, ww, j + 2);
            float w3 = __shfl_sync(FULLM, ww, j + 3);
            float w4 = __shfl_sync(FULLM, ww, j + 4);
            float w5 = __shfl_sync(FULLM, ww, j + 5);
            float w6 = __shfl_sync(FULLM, ww, j + 6);
            float w7 = __shfl_sync(FULLM, ww, j + 7);
            uint2 v0 = __ldg(&src[(size_t)c0 * 32 + lane]);
            uint2 v1 = __ldg(&src[(size_t)c1 * 32 + lane]);
            uint2 v2 = __ldg(&src[(size_t)c2 * 32 + lane]);
            uint2 v3 = __ldg(&src[(size_t)c3 * 32 + lane]);
            uint2 v4 = __ldg(&src[(size_t)c4 * 32 + lane]);
            uint2 v5 = __ldg(&src[(size_t)c5 * 32 + lane]);
            uint2 v6 = __ldg(&src[(size_t)c6 * 32 + lane]);
            uint2 v7 = __ldg(&src[(size_t)c7 * 32 + lane]);
            float fx, fy, fz, fw;
            unpack4h(v0, fx, fy, fz, fw); ax = fmaf(w0, fx, ax); ay = fmaf(w0, fy, ay); az = fmaf(w0, fz, az); aw = fmaf(w0, fw, aw);
            unpack4h(v1, fx, fy, fz, fw); ax = fmaf(w1, fx, ax); ay = fmaf(w1, fy, ay); az = fmaf(w1, fz, az); aw = fmaf(w1, fw, aw);
            unpack4h(v2, fx, fy, fz, fw); ax = fmaf(w2, fx, ax); ay = fmaf(w2, fy, ay); az = fmaf(w2, fz, az); aw = fmaf(w2, fw, aw);
            unpack4h(v3, fx, fy, fz, fw); ax = fmaf(w3, fx, ax); ay = fmaf(w3, fy, ay); az = fmaf(w3, fz, az); aw = fmaf(w3, fw, aw);
            unpack4h(v4, fx, fy, fz, fw); ax = fmaf(w4, fx, ax); ay = fmaf(w4, fy, ay); az = fmaf(w4, fz, az); aw = fmaf(w4, fw, aw);
            unpack4h(v5, fx, fy, fz, fw); ax = fmaf(w5, fx, ax); ay = fmaf(w5, fy, ay); az = fmaf(w5, fz, az); aw = fmaf(w5, fw, aw);
            unpack4h(v6, fx, fy, fz, fw); ax = fmaf(w6, fx, ax); ay = fmaf(w6, fy, ay); az = fmaf(w6, fz, az); aw = fmaf(w6, fw, aw);
            unpack4h(v7, fx, fy, fz, fw); ax = fmaf(w7, fx, ax); ay = fmaf(w7, fy, ay); az = fmaf(w7, fz, az); aw = fmaf(w7, fw, aw);
        }
        for (; j < m; ++j) {
            int   c0 = __shfl_sync(FULLM, cc, j);
            float w0 = __shfl_sync(FULLM, ww, j);
            uint2 v0 = __ldg(&src[(size_t)c0 * 32 + lane]);
            float fx, fy, fz, fw;
            unpack4h(v0, fx, fy, fz, fw);
            ax = fmaf(w0, fx, ax); ay = fmaf(w0, fy, ay); az = fmaf(w0, fz, az); aw = fmaf(w0, fw, aw);
        }
    }
}

// ---------------- propagate stages 0/1: warp per node, half in/out -----------
template <int STAGE>
__global__ void k_prop(const float4* __restrict__ xin) {
    const int gw   = (blockIdx.x * blockDim.x + threadIdx.x) >> 5;
    const int lane = threadIdx.x & 31;
    if (gw >= NN) return;
    const uint2* __restrict__ src = (STAGE == 0) ? g_xh : g_hA;
    float ax, ay, az, aw;
    gather_node(src, g_rowptr[gw], g_rowptr[gw + 1], lane, ax, ay, az, aw);
    const size_t o = (size_t)gw * 32 + lane;
    if (STAGE == 0) g_hA[o] = pack4h(ax, ay, az, aw);
    else            g_hB[o] = pack4h(ax, ay, az, aw);
}

// ---------------- stage 2 fused with GEMV: acc -> out = acc@W^T + b ----------
__global__ void __launch_bounds__(256) k_prop2_gemv(const float4* __restrict__ xin,
                                                    const float* __restrict__ W,
                                                    const float* __restrict__ b,
                                                    float* __restrict__ out) {
    __shared__ float Wt[HID * NOUT];  // Wt[k*64 + o] (32 KB)
    __shared__ float bsh[NOUT];
    for (int idx = threadIdx.x; idx < NOUT * HID; idx += 256) {
        int o = idx >> 7, k = idx & 127;            // W row-major [o][k]
        Wt[k * NOUT + o] = W[idx];
    }
    if (threadIdx.x < NOUT) bsh[threadIdx.x] = b[threadIdx.x];
    __syncthreads();

    const int lane = threadIdx.x & 31;
    const int warpsTotal = gridDim.x * (256 / 32);
    for (int gw = (blockIdx.x * 256 + threadIdx.x) >> 5; gw < NN; gw += warpsTotal) {
        float ax, ay, az, aw;
        gather_node(g_hB, g_rowptr[gw], g_rowptr[gw + 1], lane, ax, ay, az, aw);

        // acc = 0.25*(x + hA + hB + h3), lane holds k in [4*lane, 4*lane+3]
        const size_t o = (size_t)gw * 32 + lane;
        float4 xv = xin[o];
        float a0, a1, a2, a3, b0, b1, b2, b3;
        unpack4h(__ldg(&g_hA[o]), a0, a1, a2, a3);
        unpack4h(__ldg(&g_hB[o]), b0, b1, b2, b3);
        float4 acc4;
        acc4.x = 0.25f * (xv.x + a0 + b0 + ax);
        acc4.y = 0.25f * (xv.y + a1 + b1 + ay);
        acc4.z = 0.25f * (xv.z + a2 + b2 + az);
        acc4.w = 0.25f * (xv.w + a3 + b3 + aw);

        // warp GEMV: this lane produces outputs (2*lane, 2*lane+1)
        unsigned long long s2 = 0ull;
        #pragma unroll
        for (int sl = 0; sl < 32; ++sl) {
            float q0 = __shfl_sync(FULLM, acc4.x, sl);
            float q1 = __shfl_sync(FULLM, acc4.y, sl);
            float q2 = __shfl_sync(FULLM, acc4.z, sl);
            float q3 = __shfl_sync(FULLM, acc4.w, sl);
            const unsigned long long* w2 =
                reinterpret_cast<const unsigned long long*>(&Wt[(4 * sl) * NOUT + 2 * lane]);
            unsigned long long ap;
            asm("mov.b64 %0, {%1, %2};" : "=l"(ap) : "f"(q0), "f"(q0));
            asm("fma.rn.f32x2 %0, %1, %2, %0;" : "+l"(s2) : "l"(ap), "l"(w2[0]));
            asm("mov.b64 %0, {%1, %2};" : "=l"(ap) : "f"(q1), "f"(q1));
            asm("fma.rn.f32x2 %0, %1, %2, %0;" : "+l"(s2) : "l"(ap), "l"(w2[NOUT / 2]));
            asm("mov.b64 %0, {%1, %2};" : "=l"(ap) : "f"(q2), "f"(q2));
            asm("fma.rn.f32x2 %0, %1, %2, %0;" : "+l"(s2) : "l"(ap), "l"(w2[NOUT]));
            asm("mov.b64 %0, {%1, %2};" : "=l"(ap) : "f"(q3), "f"(q3));
            asm("fma.rn.f32x2 %0, %1, %2, %0;" : "+l"(s2) : "l"(ap), "l"(w2[3 * NOUT / 2]));
        }
        float r0, r1;
        asm("mov.b64 {%0, %1}, %2;" : "=f"(r0), "=f"(r1) : "l"(s2));
        float2 res = make_float2(r0 + bsh[2 * lane], r1 + bsh[2 * lane + 1]);
        *reinterpret_cast<float2*>(out + (size_t)gw * NOUT + 2 * lane) = res;
    }
}

// ---------------- launch -----------------------------------------------------
extern "C" void kernel_launch(void* const* d_in, const int* in_sizes, int n_in,
                              void* d_out, int out_size) {
    const float* x   = (const float*)d_in[0];   // [NN, HID]
    const int*   ei  = (const int*)d_in[1];     // [2, NE] int32
    const float* W   = (const float*)d_in[2];   // [NOUT, HID]
    const float* b   = (const float*)d_in[3];   // [NOUT]
    float*       out = (float*)d_out;           // [NN, NOUT]

    const int TB = 256;
    const int gX = (NN * 32 + TB - 1) / TB;
    const int gN = (NN + TB - 1) / TB;
    const int gE = (NE + TB - 1) / TB;
    const int gP = (NN * 32 + TB - 1) / TB;   // warp per node, stages 0/1
    const int gF = 148 * 8;                    // grid-stride fused stage 2

    const float4* x4 = (const float4*)x;

    k_x2h<<<gX, TB>>>(x4);          // x -> half, zero counts
    k_count<<<gE, TB>>>(ei);
    k_scan<<<1, 1024>>>();
    k_prep<<<gN, TB>>>();
    k_scatter<<<gE, TB>>>(ei);

    k_prop<0><<<gP, TB>>>(x4);      // xh -> hA
    k_prop<1><<<gP, TB>>>(x4);      // hA -> hB
    k_prop2_gemv<<<gF, TB>>>(x4, W, b, out);  // hB -> mean -> GEMV -> out

    (void)in_sizes; (void)n_in; (void)out_size;
}

// round 9
// speedup vs baseline: 1.3103x; 1.3103x over previous
#include <cuda_runtime.h>
#include <cuda_fp16.h>

#define NN   100000
#define NE   1600000
#define HID  128
#define NOUT 64
#define FULLM 0xffffffffu
#define SCAN_B 1024
#define NB_SCAN ((NN + SCAN_B - 1) / SCAN_B)   // 98

// ---------------- scratch (device globals; no allocations allowed) -----------
__device__ int   g_cnt[NN];
__device__ int   g_tmp[NN];               // block-local inclusive scan
__device__ int   g_bsum[NB_SCAN];
__device__ int   g_boff[NB_SCAN];
__device__ int   g_rowptr[NN + 1];
__device__ int   g_cursor[NN];
__device__ float g_dis[NN];
__device__ uint2 g_edge[NE];              // {col, norm bits}
__device__ uint2 g_xh[(size_t)NN * 32];   // x in half  (128 half = 32 uint2)
__device__ uint2 g_hA[(size_t)NN * 32];   // h1 in half
__device__ uint2 g_hB[(size_t)NN * 32];   // h2 in half
__device__ float g_acc[(size_t)NN * HID]; // mean(x,h1,h2,h3) fp32

__device__ __forceinline__ int clampN(int v) {
    v = v < 0 ? 0 : v;
    return v >= NN ? NN - 1 : v;
}

__device__ __forceinline__ uint2 pack4h(float a, float b, float c, float d) {
    __half2 h0 = __floats2half2_rn(a, b);
    __half2 h1 = __floats2half2_rn(c, d);
    uint2 r;
    r.x = *reinterpret_cast<unsigned*>(&h0);
    r.y = *reinterpret_cast<unsigned*>(&h1);
    return r;
}

__device__ __forceinline__ void unpack4h(uint2 v, float& a, float& b, float& c, float& d) {
    __half2 h0 = *reinterpret_cast<__half2*>(&v.x);
    __half2 h1 = *reinterpret_cast<__half2*>(&v.y);
    float2 f0 = __half22float2(h0);
    float2 f1 = __half22float2(h1);
    a = f0.x; b = f0.y; c = f1.x; d = f1.y;
}

// ---------------- x -> half conversion (+ zero counts, fused) ----------------
__global__ void k_x2h(const float4* __restrict__ x4) {
    int i = blockIdx.x * blockDim.x + threadIdx.x;
    if (i < NN) g_cnt[i] = 0;
    if (i < NN * 32) {
        float4 v = x4[i];
        g_xh[i] = pack4h(v.x, v.y, v.z, v.w);
    }
}

// ---------------- CSR build ---------------------------------------------------
__global__ void k_count(const int* __restrict__ ei) {
    int e = blockIdx.x * blockDim.x + threadIdx.x;
    if (e < NE) atomicAdd(&g_cnt[clampN(ei[e])], 1);
}

// block-level inclusive scan helper (1024 threads)
__device__ __forceinline__ int block_incl_scan(int v, int* s_warp) {
    const int lane = threadIdx.x & 31, wid = threadIdx.x >> 5;
    int x = v;
    #pragma unroll
    for (int d = 1; d < 32; d <<= 1) {
        int t = __shfl_up_sync(FULLM, x, d);
        if (lane >= d) x += t;
    }
    if (lane == 31) s_warp[wid] = x;
    __syncthreads();
    if (wid == 0) {
        int y = s_warp[lane];
        #pragma unroll
        for (int d = 1; d < 32; d <<= 1) {
            int t = __shfl_up_sync(FULLM, y, d);
            if (lane >= d) y += t;
        }
        s_warp[lane] = y;
    }
    __syncthreads();
    return x + (wid > 0 ? s_warp[wid - 1] : 0);
}

// pass 1: per-block inclusive scan of g_cnt -> g_tmp, block totals -> g_bsum
__global__ void __launch_bounds__(SCAN_B) k_scan1() {
    __shared__ int s_warp[32];
    int i = blockIdx.x * SCAN_B + threadIdx.x;
    int v = (i < NN) ? g_cnt[i] : 0;
    int incl = block_incl_scan(v, s_warp);
    if (i < NN) g_tmp[i] = incl;
    if (threadIdx.x == SCAN_B - 1) g_bsum[blockIdx.x] = incl;
}

// pass 2: single small block scans the 98 block sums -> exclusive offsets
__global__ void __launch_bounds__(128) k_scan2() {
    __shared__ int s_warp[32];
    const int lane = threadIdx.x & 31, wid = threadIdx.x >> 5;
    int v = (threadIdx.x < NB_SCAN) ? g_bsum[threadIdx.x] : 0;
    int x = v;
    #pragma unroll
    for (int d = 1; d < 32; d <<= 1) {
        int t = __shfl_up_sync(FULLM, x, d);
        if (lane >= d) x += t;
    }
    if (lane == 31) s_warp[wid] = x;
    __syncthreads();
    if (wid == 0 && lane < 4) {
        int y = s_warp[lane];
        #pragma unroll
        for (int d = 1; d < 4; d <<= 1) {
            int t = __shfl_up_sync(0xfu, y, d);
            if (lane >= d) y += t;
        }
        s_warp[lane] = y;
    }
    __syncthreads();
    int incl = x + (wid > 0 ? s_warp[wid - 1] : 0);
    if (threadIdx.x < NB_SCAN) g_boff[threadIdx.x] = incl - v;  // exclusive
}

// pass 3: finalize rowptr + cursor + dis (fuses old k_prep)
__global__ void __launch_bounds__(SCAN_B) k_scan3() {
    int i = blockIdx.x * SCAN_B + threadIdx.x;
    if (i == 0) g_rowptr[0] = 0;
    if (i < NN) {
        int off  = g_boff[blockIdx.x];
        int incl = g_tmp[i] + off;
        int cnt  = g_cnt[i];
        g_rowptr[i + 1] = incl;
        g_cursor[i]     = incl - cnt;
        g_dis[i]        = rsqrtf(fmaxf((float)cnt, 1.0f));
    }
}

__global__ void k_scatter(const int* __restrict__ ei) {
    int e = blockIdx.x * blockDim.x + threadIdx.x;
    if (e < NE) {
        int r = clampN(ei[e]);
        int c = clampN(ei[NE + e]);
        int pos = atomicAdd(&g_cursor[r], 1);
        float nrm = g_dis[r] * g_dis[c];
        g_edge[pos] = make_uint2((unsigned)c, __float_as_uint(nrm));
    }
}

// ---------------- gather core (warp computes one node's aggregation) ---------
__device__ __forceinline__ void gather_node(const uint2* __restrict__ src,
                                            int beg, int end, int lane,
                                            float& ax, float& ay, float& az, float& aw) {
    ax = 0.f; ay = 0.f; az = 0.f; aw = 0.f;
    for (int e0 = beg; e0 < end; e0 += 32) {
        int e = e0 + lane;
        int   cc = 0;
        float ww = 0.f;
        if (e < end) { uint2 ed = g_edge[e]; cc = (int)ed.x; ww = __uint_as_float(ed.y); }
        int m = end - e0; if (m > 32) m = 32;
        int j = 0;
        for (; j + 8 <= m; j += 8) {
            int   c0 = __shfl_sync(FULLM, cc, j + 0);
            int   c1 = __shfl_sync(FULLM, cc, j + 1);
            int   c2 = __shfl_sync(FULLM, cc, j + 2);
            int   c3 = __shfl_sync(FULLM, cc, j + 3);
            int   c4 = __shfl_sync(FULLM, cc, j + 4);
            int   c5 = __shfl_sync(FULLM, cc, j + 5);
            int   c6 = __shfl_sync(FULLM, cc, j + 6);
            int   c7 = __shfl_sync(FULLM, cc, j + 7);
            float w0 = __shfl_sync(FULLM, ww, j + 0);
            float w1 = __shfl_sync(FULLM, ww, j + 1);
            float w2 = __shfl_sync(FULLM, ww, j + 2);
            float w3 = __shfl_sync(FULLM, ww, j + 3);
            float w4 = __shfl_sync(FULLM, ww, j + 4);
            float w5 = __shfl_sync(FULLM, ww, j + 5);
            float w6 = __shfl_sync(FULLM, ww, j + 6);
            float w7 = __shfl_sync(FULLM, ww, j + 7);
            uint2 v0 = __ldg(&src[(size_t)c0 * 32 + lane]);
            uint2 v1 = __ldg(&src[(size_t)c1 * 32 + lane]);
            uint2 v2 = __ldg(&src[(size_t)c2 * 32 + lane]);
            uint2 v3 = __ldg(&src[(size_t)c3 * 32 + lane]);
            uint2 v4 = __ldg(&src[(size_t)c4 * 32 + lane]);
            uint2 v5 = __ldg(&src[(size_t)c5 * 32 + lane]);
            uint2 v6 = __ldg(&src[(size_t)c6 * 32 + lane]);
            uint2 v7 = __ldg(&src[(size_t)c7 * 32 + lane]);
            float fx, fy, fz, fw;
            unpack4h(v0, fx, fy, fz, fw); ax = fmaf(w0, fx, ax); ay = fmaf(w0, fy, ay); az = fmaf(w0, fz, az); aw = fmaf(w0, fw, aw);
            unpack4h(v1, fx, fy, fz, fw); ax = fmaf(w1, fx, ax); ay = fmaf(w1, fy, ay); az = fmaf(w1, fz, az); aw = fmaf(w1, fw, aw);
            unpack4h(v2, fx, fy, fz, fw); ax = fmaf(w2, fx, ax); ay = fmaf(w2, fy, ay); az = fmaf(w2, fz, az); aw = fmaf(w2, fw, aw);
            unpack4h(v3, fx, fy, fz, fw); ax = fmaf(w3, fx, ax); ay = fmaf(w3, fy, ay); az = fmaf(w3, fz, az); aw = fmaf(w3, fw, aw);
            unpack4h(v4, fx, fy, fz, fw); ax = fmaf(w4, fx, ax); ay = fmaf(w4, fy, ay); az = fmaf(w4, fz, az); aw = fmaf(w4, fw, aw);
            unpack4h(v5, fx, fy, fz, fw); ax = fmaf(w5, fx, ax); ay = fmaf(w5, fy, ay); az = fmaf(w5, fz, az); aw = fmaf(w5, fw, aw);
            unpack4h(v6, fx, fy, fz, fw); ax = fmaf(w6, fx, ax); ay = fmaf(w6, fy, ay); az = fmaf(w6, fz, az); aw = fmaf(w6, fw, aw);
            unpack4h(v7, fx, fy, fz, fw); ax = fmaf(w7, fx, ax); ay = fmaf(w7, fy, ay); az = fmaf(w7, fz, az); aw = fmaf(w7, fw, aw);
        }
        for (; j < m; ++j) {
            int   c0 = __shfl_sync(FULLM, cc, j);
            float w0 = __shfl_sync(FULLM, ww, j);
            uint2 v0 = __ldg(&src[(size_t)c0 * 32 + lane]);
            float fx, fy, fz, fw;
            unpack4h(v0, fx, fy, fz, fw);
            ax = fmaf(w0, fx, ax); ay = fmaf(w0, fy, ay); az = fmaf(w0, fz, az); aw = fmaf(w0, fw, aw);
        }
    }
}

// ---------------- propagate: warp per node, half rows, fp32 accum ------------
// STAGE 0: g_xh -> g_hA; STAGE 1: g_hA -> g_hB; STAGE 2: g_hB -> g_acc (mean)
template <int STAGE>
__global__ void k_prop(const float4* __restrict__ xin) {
    const int gw   = (blockIdx.x * blockDim.x + threadIdx.x) >> 5;
    const int lane = threadIdx.x & 31;
    if (gw >= NN) return;
    const uint2* __restrict__ src =
        (STAGE == 0) ? g_xh : (STAGE == 1) ? g_hA : g_hB;
    float ax, ay, az, aw;
    gather_node(src, g_rowptr[gw], g_rowptr[gw + 1], lane, ax, ay, az, aw);
    const size_t o = (size_t)gw * 32 + lane;
    if (STAGE == 2) {
        float4 xv = xin[o];
        float a0, a1, a2, a3, b0, b1, b2, b3;
        unpack4h(__ldg(&g_hA[o]), a0, a1, a2, a3);
        unpack4h(__ldg(&g_hB[o]), b0, b1, b2, b3);
        float4 r;
        r.x = 0.25f * (xv.x + a0 + b0 + ax);
        r.y = 0.25f * (xv.y + a1 + b1 + ay);
        r.z = 0.25f * (xv.z + a2 + b2 + az);
        r.w = 0.25f * (xv.w + a3 + b3 + aw);
        ((float4*)g_acc)[o] = r;
    } else if (STAGE == 1) {
        g_hB[o] = pack4h(ax, ay, az, aw);
    } else {
        g_hA[o] = pack4h(ax, ay, az, aw);
    }
}

// ---------------- final dense: out = acc @ W^T + b (packed f32x2 FMA) --------
#define WT_PITCH 66

__global__ void __launch_bounds__(128) k_gemm(const float* __restrict__ W,
                                              const float* __restrict__ b,
                                              float* __restrict__ out) {
    __shared__ float Wt[HID * WT_PITCH];
    __shared__ float bsh[NOUT];
    const int tid = threadIdx.x;
    for (int idx = tid; idx < NOUT * HID; idx += 128) {
        int o = idx >> 7;
        int k = idx & 127;
        Wt[k * WT_PITCH + o] = W[idx];
    }
    if (tid < NOUT) bsh[tid] = b[tid];
    __syncthreads();

    const int v = blockIdx.x * 128 + tid;
    if (v >= NN) return;

    const float4* a4 = (const float4*)g_acc + (size_t)v * 32;

    unsigned long long s2[32];
    #pragma unroll
    for (int i = 0; i < 32; ++i) s2[i] = 0ull;

    #pragma unroll 4
    for (int kk = 0; kk < 32; ++kk) {
        float4 a = __ldg(&a4[kk]);
        #pragma unroll
        for (int d = 0; d < 4; ++d) {
            float av = (d == 0) ? a.x : (d == 1) ? a.y : (d == 2) ? a.z : a.w;
            unsigned long long ap;
            asm("mov.b64 %0, {%1, %2};" : "=l"(ap) : "f"(av), "f"(av));
            const unsigned long long* w2 =
                reinterpret_cast<const unsigned long long*>(&Wt[(kk * 4 + d) * WT_PITCH]);
            #pragma unroll
            for (int o2 = 0; o2 < 32; ++o2) {
                asm("fma.rn.f32x2 %0, %1, %2, %0;" : "+l"(s2[o2]) : "l"(ap), "l"(w2[o2]));
            }
        }
    }

    float4* op = (float4*)(out + (size_t)v * NOUT);
    #pragma unroll
    for (int q = 0; q < 16; ++q) {
        float l0, h0, l1, h1;
        asm("mov.b64 {%0, %1}, %2;" : "=f"(l0), "=f"(h0) : "l"(s2[2 * q]));
        asm("mov.b64 {%0, %1}, %2;" : "=f"(l1), "=f"(h1) : "l"(s2[2 * q + 1]));
        float4 r = make_float4(l0 + bsh[4 * q + 0], h0 + bsh[4 * q + 1],
                               l1 + bsh[4 * q + 2], h1 + bsh[4 * q + 3]);
        op[q] = r;
    }
}

// ---------------- launch -----------------------------------------------------
extern "C" void kernel_launch(void* const* d_in, const int* in_sizes, int n_in,
                              void* d_out, int out_size) {
    const float* x   = (const float*)d_in[0];   // [NN, HID]
    const int*   ei  = (const int*)d_in[1];     // [2, NE] int32
    const float* W   = (const float*)d_in[2];   // [NOUT, HID]
    const float* b   = (const float*)d_in[3];   // [NOUT]
    float*       out = (float*)d_out;           // [NN, NOUT]

    const int TB = 256;
    const int gX = (NN * 32 + TB - 1) / TB;
    const int gE = (NE + TB - 1) / TB;
    const int gP = (NN * 32 + TB - 1) / TB;   // warp per node

    const float4* x4 = (const float4*)x;

    k_x2h<<<gX, TB>>>(x4);          // x -> half, zero counts
    k_count<<<gE, TB>>>(ei);
    k_scan1<<<NB_SCAN, SCAN_B>>>();
    k_scan2<<<1, 128>>>();
    k_scan3<<<NB_SCAN, SCAN_B>>>(); // rowptr + cursor + dis
    k_scatter<<<gE, TB>>>(ei);

    k_prop<0><<<gP, TB>>>(x4);      // xh -> hA
    k_prop<1><<<gP, TB>>>(x4);      // hA -> hB
    k_prop<2><<<gP, TB>>>(x4);      // hB -> acc (fused mean, fp32)

    const int gG = (NN + 127) / 128;
    k_gemm<<<gG, 128>>>(W, b, out);

    (void)in_sizes; (void)n_in; (void)out_size;
}

// round 10
// speedup vs baseline: 1.5283x; 1.1664x over previous
#include <cuda_runtime.h>
#include <cuda_fp16.h>

#define NN   100000
#define NE   1600000
#define HID  128
#define NOUT 64
#define FULLM 0xffffffffu
#define SCAN_B 1024
#define NB_SCAN ((NN + SCAN_B - 1) / SCAN_B)   // 98
#define WT_PITCH 66

// ---------------- scratch (device globals; no allocations allowed) -----------
__device__ int      g_cnt[NN];
__device__ int      g_tmp[NN];
__device__ int      g_bsum[NB_SCAN];
__device__ int      g_boff[NB_SCAN];
__device__ int      g_rowptr[NN + 1];
__device__ int      g_cursor[NN];
__device__ float    g_dis[NN];
__device__ uint2    g_edge[NE];                  // {col, norm bits}
__device__ float    g_yf[(size_t)NN * NOUT];     // y = x @ W^T, fp32
__device__ unsigned g_yh[(size_t)NN * 32];       // y in half  (64 half = 32 u32)
__device__ unsigned g_hA[(size_t)NN * 32];       // A y
__device__ unsigned g_hB[(size_t)NN * 32];       // A^2 y

__device__ __forceinline__ int clampN(int v) {
    v = v < 0 ? 0 : v;
    return v >= NN ? NN - 1 : v;
}

__device__ __forceinline__ unsigned pack2h(float a, float b) {
    __half2 h = __floats2half2_rn(a, b);
    return *reinterpret_cast<unsigned*>(&h);
}

__device__ __forceinline__ float2 unpack2h(unsigned v) {
    __half2 h = *reinterpret_cast<__half2*>(&v);
    return __half22float2(h);
}

// ---------------- y = x @ W^T (fp32+half out), fused cnt zeroing -------------
__global__ void __launch_bounds__(128) k_gemm_y(const float* __restrict__ x,
                                                const float* __restrict__ W) {
    __shared__ float Wt[HID * WT_PITCH];  // Wt[k*66 + o]
    const int tid = threadIdx.x;
    for (int idx = tid; idx < NOUT * HID; idx += 128) {
        int o = idx >> 7, k = idx & 127;   // W row-major [o][k]
        Wt[k * WT_PITCH + o] = W[idx];
    }
    __syncthreads();

    const int v = blockIdx.x * 128 + tid;
    if (v < NN) g_cnt[v] = 0;
    if (v >= NN) return;

    const float4* a4 = (const float4*)x + (size_t)v * 32;

    unsigned long long s2[32];  // pairs (2q, 2q+1)
    #pragma unroll
    for (int i = 0; i < 32; ++i) s2[i] = 0ull;

    #pragma unroll 4
    for (int kk = 0; kk < 32; ++kk) {
        float4 a = __ldg(&a4[kk]);
        #pragma unroll
        for (int d = 0; d < 4; ++d) {
            float av = (d == 0) ? a.x : (d == 1) ? a.y : (d == 2) ? a.z : a.w;
            unsigned long long ap;
            asm("mov.b64 %0, {%1, %2};" : "=l"(ap) : "f"(av), "f"(av));
            const unsigned long long* w2 =
                reinterpret_cast<const unsigned long long*>(&Wt[(kk * 4 + d) * WT_PITCH]);
            #pragma unroll
            for (int q = 0; q < 32; ++q) {
                asm("fma.rn.f32x2 %0, %1, %2, %0;" : "+l"(s2[q]) : "l"(ap), "l"(w2[q]));
            }
        }
    }

    float2*   yf = (float2*)g_yf + (size_t)v * 32;
    unsigned  yh[32];
    #pragma unroll
    for (int q = 0; q < 32; ++q) {
        float l, h;
        asm("mov.b64 {%0, %1}, %2;" : "=f"(l), "=f"(h) : "l"(s2[q]));
        yf[q] = make_float2(l, h);
        yh[q] = pack2h(l, h);
    }
    uint4* yh4 = (uint4*)(g_yh + (size_t)v * 32);
    #pragma unroll
    for (int q = 0; q < 8; ++q)
        yh4[q] = make_uint4(yh[4 * q], yh[4 * q + 1], yh[4 * q + 2], yh[4 * q + 3]);
}

// ---------------- CSR build ---------------------------------------------------
__global__ void k_count(const int* __restrict__ ei) {
    int e = blockIdx.x * blockDim.x + threadIdx.x;
    if (e < NE) atomicAdd(&g_cnt[clampN(ei[e])], 1);
}

__device__ __forceinline__ int block_incl_scan(int v, int* s_warp) {
    const int lane = threadIdx.x & 31, wid = threadIdx.x >> 5;
    int x = v;
    #pragma unroll
    for (int d = 1; d < 32; d <<= 1) {
        int t = __shfl_up_sync(FULLM, x, d);
        if (lane >= d) x += t;
    }
    if (lane == 31) s_warp[wid] = x;
    __syncthreads();
    if (wid == 0) {
        int y = s_warp[lane];
        #pragma unroll
        for (int d = 1; d < 32; d <<= 1) {
            int t = __shfl_up_sync(FULLM, y, d);
            if (lane >= d) y += t;
        }
        s_warp[lane] = y;
    }
    __syncthreads();
    return x + (wid > 0 ? s_warp[wid - 1] : 0);
}

__global__ void __launch_bounds__(SCAN_B) k_scan1() {
    __shared__ int s_warp[32];
    int i = blockIdx.x * SCAN_B + threadIdx.x;
    int v = (i < NN) ? g_cnt[i] : 0;
    int incl = block_incl_scan(v, s_warp);
    if (i < NN) g_tmp[i] = incl;
    if (threadIdx.x == SCAN_B - 1) g_bsum[blockIdx.x] = incl;
}

__global__ void __launch_bounds__(128) k_scan2() {
    __shared__ int s_warp[32];
    const int lane = threadIdx.x & 31, wid = threadIdx.x >> 5;
    int v = (threadIdx.x < NB_SCAN) ? g_bsum[threadIdx.x] : 0;
    int x = v;
    #pragma unroll
    for (int d = 1; d < 32; d <<= 1) {
        int t = __shfl_up_sync(FULLM, x, d);
        if (lane >= d) x += t;
    }
    if (lane == 31) s_warp[wid] = x;
    __syncthreads();
    if (wid == 0 && lane < 4) {
        int y = s_warp[lane];
        #pragma unroll
        for (int d = 1; d < 4; d <<= 1) {
            int t = __shfl_up_sync(0xfu, y, d);
            if (lane >= d) y += t;
        }
        s_warp[lane] = y;
    }
    __syncthreads();
    int incl = x + (wid > 0 ? s_warp[wid - 1] : 0);
    if (threadIdx.x < NB_SCAN) g_boff[threadIdx.x] = incl - v;
}

__global__ void __launch_bounds__(SCAN_B) k_scan3() {
    int i = blockIdx.x * SCAN_B + threadIdx.x;
    if (i == 0) g_rowptr[0] = 0;
    if (i < NN) {
        int off  = g_boff[blockIdx.x];
        int incl = g_tmp[i] + off;
        int cnt  = g_cnt[i];
        g_rowptr[i + 1] = incl;
        g_cursor[i]     = incl - cnt;
        g_dis[i]        = rsqrtf(fmaxf((float)cnt, 1.0f));
    }
}

__global__ void k_scatter(const int* __restrict__ ei) {
    int e = blockIdx.x * blockDim.x + threadIdx.x;
    if (e < NE) {
        int r = clampN(ei[e]);
        int c = clampN(ei[NE + e]);
        int pos = atomicAdd(&g_cursor[r], 1);
        float nrm = g_dis[r] * g_dis[c];
        g_edge[pos] = make_uint2((unsigned)c, __float_as_uint(nrm));
    }
}

// ---------------- gather core: warp per node, 64-dim half rows ----------------
__device__ __forceinline__ float2 gather64(const unsigned* __restrict__ src,
                                           int beg, int end, int lane) {
    float ax = 0.f, ay = 0.f;
    for (int e0 = beg; e0 < end; e0 += 32) {
        int e = e0 + lane;
        int   cc = 0;
        float ww = 0.f;
        if (e < end) { uint2 ed = g_edge[e]; cc = (int)ed.x; ww = __uint_as_float(ed.y); }
        int m = end - e0; if (m > 32) m = 32;
        int j = 0;
        for (; j + 8 <= m; j += 8) {
            int   c0 = __shfl_sync(FULLM, cc, j + 0);
            int   c1 = __shfl_sync(FULLM, cc, j + 1);
            int   c2 = __shfl_sync(FULLM, cc, j + 2);
            int   c3 = __shfl_sync(FULLM, cc, j + 3);
            int   c4 = __shfl_sync(FULLM, cc, j + 4);
            int   c5 = __shfl_sync(FULLM, cc, j + 5);
            int   c6 = __shfl_sync(FULLM, cc, j + 6);
            int   c7 = __shfl_sync(FULLM, cc, j + 7);
            float w0 = __shfl_sync(FULLM, ww, j + 0);
            float w1 = __shfl_sync(FULLM, ww, j + 1);
            float w2 = __shfl_sync(FULLM, ww, j + 2);
            float w3 = __shfl_sync(FULLM, ww, j + 3);
            float w4 = __shfl_sync(FULLM, ww, j + 4);
            float w5 = __shfl_sync(FULLM, ww, j + 5);
            float w6 = __shfl_sync(FULLM, ww, j + 6);
            float w7 = __shfl_sync(FULLM, ww, j + 7);
            unsigned v0 = __ldg(&src[(size_t)c0 * 32 + lane]);
            unsigned v1 = __ldg(&src[(size_t)c1 * 32 + lane]);
            unsigned v2 = __ldg(&src[(size_t)c2 * 32 + lane]);
            unsigned v3 = __ldg(&src[(size_t)c3 * 32 + lane]);
            unsigned v4 = __ldg(&src[(size_t)c4 * 32 + lane]);
            unsigned v5 = __ldg(&src[(size_t)c5 * 32 + lane]);
            unsigned v6 = __ldg(&src[(size_t)c6 * 32 + lane]);
            unsigned v7 = __ldg(&src[(size_t)c7 * 32 + lane]);
            float2 f;
            f = unpack2h(v0); ax = fmaf(w0, f.x, ax); ay = fmaf(w0, f.y, ay);
            f = unpack2h(v1); ax = fmaf(w1, f.x, ax); ay = fmaf(w1, f.y, ay);
            f = unpack2h(v2); ax = fmaf(w2, f.x, ax); ay = fmaf(w2, f.y, ay);
            f = unpack2h(v3); ax = fmaf(w3, f.x, ax); ay = fmaf(w3, f.y, ay);
            f = unpack2h(v4); ax = fmaf(w4, f.x, ax); ay = fmaf(w4, f.y, ay);
            f = unpack2h(v5); ax = fmaf(w5, f.x, ax); ay = fmaf(w5, f.y, ay);
            f = unpack2h(v6); ax = fmaf(w6, f.x, ax); ay = fmaf(w6, f.y, ay);
            f = unpack2h(v7); ax = fmaf(w7, f.x, ax); ay = fmaf(w7, f.y, ay);
        }
        for (; j < m; ++j) {
            int   c0 = __shfl_sync(FULLM, cc, j);
            float w0 = __shfl_sync(FULLM, ww, j);
            float2 f = unpack2h(__ldg(&src[(size_t)c0 * 32 + lane]));
            ax = fmaf(w0, f.x, ax); ay = fmaf(w0, f.y, ay);
        }
    }
    return make_float2(ax, ay);
}

// ---------------- propagate stages (64-dim). STAGE 2 writes final out --------
template <int STAGE>
__global__ void k_prop64(const float* __restrict__ bias, float* __restrict__ out) {
    const int gw   = (blockIdx.x * blockDim.x + threadIdx.x) >> 5;
    const int lane = threadIdx.x & 31;
    if (gw >= NN) return;
    const unsigned* __restrict__ src =
        (STAGE == 0) ? g_yh : (STAGE == 1) ? g_hA : g_hB;
    float2 a = gather64(src, g_rowptr[gw], g_rowptr[gw + 1], lane);
    const size_t o = (size_t)gw * 32 + lane;
    if (STAGE == 2) {
        float2 yv = ((const float2*)g_yf)[o];
        float2 h1 = unpack2h(__ldg(&g_hA[o]));
        float2 h2 = unpack2h(__ldg(&g_hB[o]));
        float2 bv = __ldg((const float2*)bias + lane);
        float2 r;
        r.x = fmaf(0.25f, yv.x + h1.x + h2.x + a.x, bv.x);
        r.y = fmaf(0.25f, yv.y + h1.y + h2.y + a.y, bv.y);
        ((float2*)out)[o] = r;
    } else if (STAGE == 1) {
        g_hB[o] = pack2h(a.x, a.y);
    } else {
        g_hA[o] = pack2h(a.x, a.y);
    }
}

// ---------------- launch -----------------------------------------------------
extern "C" void kernel_launch(void* const* d_in, const int* in_sizes, int n_in,
                              void* d_out, int out_size) {
    const float* x   = (const float*)d_in[0];   // [NN, HID]
    const int*   ei  = (const int*)d_in[1];     // [2, NE] int32
    const float* W   = (const float*)d_in[2];   // [NOUT, HID]
    const float* b   = (const float*)d_in[3];   // [NOUT]
    float*       out = (float*)d_out;           // [NN, NOUT]

    const int TB = 256;
    const int gE = (NE + TB - 1) / TB;
    const int gP = (NN * 32 + TB - 1) / TB;   // warp per node
    const int gG = (NN + 127) / 128;

    k_gemm_y<<<gG, 128>>>(x, W);    // y = x@W^T (fp32+half), zero counts
    k_count<<<gE, TB>>>(ei);
    k_scan1<<<NB_SCAN, SCAN_B>>>();
    k_scan2<<<1, 128>>>();
    k_scan3<<<NB_SCAN, SCAN_B>>>();
    k_scatter<<<gE, TB>>>(ei);

    k_prop64<0><<<gP, TB>>>(b, out);   // yh -> hA
    k_prop64<1><<<gP, TB>>>(b, out);   // hA -> hB
    k_prop64<2><<<gP, TB>>>(b, out);   // hB -> out (mean + bias fused)

    (void)in_sizes; (void)n_in; (void)out_size;
}

// round 12
// speedup vs baseline: 1.6722x; 1.0942x over previous
#include <cuda_runtime.h>
#include <cuda_fp16.h>

#define NN   100000
#define NE   1600000
#define HID  128
#define NOUT 64
#define FULLM 0xffffffffu
#define SCAN_B 1024
#define NB_SCAN ((NN + SCAN_B - 1) / SCAN_B)   // 98
#define WT_PITCH 66

// ---------------- scratch (device globals; zero-initialized at load) ---------
__device__ int      g_cnt[NN];            // starts 0; re-zeroed by k_scan3
__device__ int      g_tmp[NN];
__device__ int      g_bsum[NB_SCAN];
__device__ int      g_boff[NB_SCAN];
__device__ int      g_rowptr[NN + 1];
__device__ int      g_cursor[NN];
__device__ float    g_dis[NN];            // deg^-1/2 (clamped)
__device__ float    g_d2[NN];             // dis^2
__device__ float    g_inv[NN];            // 1/dis
__device__ int      g_ecol[NE];           // edge cols (CSR order)
__device__ float    g_yf[(size_t)NN * NOUT];     // y = x @ W^T, fp32
__device__ unsigned g_yh[(size_t)NN * 32];       // dis*y in half (64 half)
__device__ unsigned g_hA[(size_t)NN * 32];       // dis^2 * S0
__device__ unsigned g_hB[(size_t)NN * 32];       // dis^2 * S1

__device__ __forceinline__ int clampN(int v) {
    v = v < 0 ? 0 : v;
    return v >= NN ? NN - 1 : v;
}

__device__ __forceinline__ unsigned pack2h(float a, float b) {
    __half2 h = __floats2half2_rn(a, b);
    return *reinterpret_cast<unsigned*>(&h);
}

__device__ __forceinline__ float2 unpack2h(unsigned v) {
    __half2 h = *reinterpret_cast<__half2*>(&v);
    return __half22float2(h);
}

// ---------------- CSR build ---------------------------------------------------
__global__ void k_count(const int* __restrict__ ei) {
    int e = blockIdx.x * blockDim.x + threadIdx.x;
    if (e < NE) atomicAdd(&g_cnt[clampN(ei[e])], 1);
}

__device__ __forceinline__ int block_incl_scan(int v, int* s_warp) {
    const int lane = threadIdx.x & 31, wid = threadIdx.x >> 5;
    int x = v;
    #pragma unroll
    for (int d = 1; d < 32; d <<= 1) {
        int t = __shfl_up_sync(FULLM, x, d);
        if (lane >= d) x += t;
    }
    if (lane == 31) s_warp[wid] = x;
    __syncthreads();
    if (wid == 0) {
        int y = s_warp[lane];
        #pragma unroll
        for (int d = 1; d < 32; d <<= 1) {
            int t = __shfl_up_sync(FULLM, y, d);
            if (lane >= d) y += t;
        }
        s_warp[lane] = y;
    }
    __syncthreads();
    return x + (wid > 0 ? s_warp[wid - 1] : 0);
}

__global__ void __launch_bounds__(SCAN_B) k_scan1() {
    __shared__ int s_warp[32];
    int i = blockIdx.x * SCAN_B + threadIdx.x;
    int v = (i < NN) ? g_cnt[i] : 0;
    int incl = block_incl_scan(v, s_warp);
    if (i < NN) g_tmp[i] = incl;
    if (threadIdx.x == SCAN_B - 1) g_bsum[blockIdx.x] = incl;
}

__global__ void __launch_bounds__(128) k_scan2() {
    __shared__ int s_warp[32];
    const int lane = threadIdx.x & 31, wid = threadIdx.x >> 5;
    int v = (threadIdx.x < NB_SCAN) ? g_bsum[threadIdx.x] : 0;
    int x = v;
    #pragma unroll
    for (int d = 1; d < 32; d <<= 1) {
        int t = __shfl_up_sync(FULLM, x, d);
        if (lane >= d) x += t;
    }
    if (lane == 31) s_warp[wid] = x;
    __syncthreads();
    if (wid == 0 && lane < 4) {
        int y = s_warp[lane];
        #pragma unroll
        for (int d = 1; d < 4; d <<= 1) {
            int t = __shfl_up_sync(0xfu, y, d);
            if (lane >= d) y += t;
        }
        s_warp[lane] = y;
    }
    __syncthreads();
    int incl = x + (wid > 0 ? s_warp[wid - 1] : 0);
    if (threadIdx.x < NB_SCAN) g_boff[threadIdx.x] = incl - v;
}

// finalize rowptr/cursor/dis/d2/inv, and re-zero g_cnt for next replay
__global__ void __launch_bounds__(SCAN_B) k_scan3() {
    int i = blockIdx.x * SCAN_B + threadIdx.x;
    if (i == 0) g_rowptr[0] = 0;
    if (i < NN) {
        int off  = g_boff[blockIdx.x];
        int incl = g_tmp[i] + off;
        int cnt  = g_cnt[i];
        float dg = fmaxf((float)cnt, 1.0f);
        float ds = rsqrtf(dg);
        g_rowptr[i + 1] = incl;
        g_cursor[i]     = incl - cnt;
        g_dis[i]        = ds;
        g_d2[i]         = 1.0f / dg;      // dis^2 exactly
        g_inv[i]        = sqrtf(dg);      // 1/dis
        g_cnt[i]        = 0;              // ready for next launch
    }
}

__global__ void k_scatter(const int* __restrict__ ei) {
    int e = blockIdx.x * blockDim.x + threadIdx.x;
    if (e < NE) {
        int r = clampN(ei[e]);
        int c = clampN(ei[NE + e]);
        int pos = atomicAdd(&g_cursor[r], 1);
        g_ecol[pos] = c;
    }
}

// ---------------- y = x @ W^T (fp32 out) + scaled half ŷ = dis*y -------------
__global__ void __launch_bounds__(128) k_gemm_y(const float* __restrict__ x,
                                                const float* __restrict__ W) {
    __shared__ float Wt[HID * WT_PITCH];  // Wt[k*66 + o]
    const int tid = threadIdx.x;
    for (int idx = tid; idx < NOUT * HID; idx += 128) {
        int o = idx >> 7, k = idx & 127;   // W row-major [o][k]
        Wt[k * WT_PITCH + o] = W[idx];
    }
    __syncthreads();

    const int v = blockIdx.x * 128 + tid;
    if (v >= NN) return;

    const float4* a4 = (const float4*)x + (size_t)v * 32;

    unsigned long long s2[32];
    #pragma unroll
    for (int i = 0; i < 32; ++i) s2[i] = 0ull;

    #pragma unroll 4
    for (int kk = 0; kk < 32; ++kk) {
        float4 a = __ldg(&a4[kk]);
        #pragma unroll
        for (int d = 0; d < 4; ++d) {
            float av = (d == 0) ? a.x : (d == 1) ? a.y : (d == 2) ? a.z : a.w;
            unsigned long long ap;
            asm("mov.b64 %0, {%1, %2};" : "=l"(ap) : "f"(av), "f"(av));
            const unsigned long long* w2 =
                reinterpret_cast<const unsigned long long*>(&Wt[(kk * 4 + d) * WT_PITCH]);
            #pragma unroll
            for (int q = 0; q < 32; ++q) {
                asm("fma.rn.f32x2 %0, %1, %2, %0;" : "+l"(s2[q]) : "l"(ap), "l"(w2[q]));
            }
        }
    }

    const float ds = g_dis[v];
    float2*  yf = (float2*)g_yf + (size_t)v * 32;
    unsigned yh[32];
    #pragma unroll
    for (int q = 0; q < 32; ++q) {
        float l, h;
        asm("mov.b64 {%0, %1}, %2;" : "=f"(l), "=f"(h) : "l"(s2[q]));
        yf[q] = make_float2(l, h);
        yh[q] = pack2h(l * ds, h * ds);
    }
    uint4* yh4 = (uint4*)(g_yh + (size_t)v * 32);
    #pragma unroll
    for (int q = 0; q < 8; ++q)
        yh4[q] = make_uint4(yh[4 * q], yh[4 * q + 1], yh[4 * q + 2], yh[4 * q + 3]);
}

// ---------------- gather: warp per node, unweighted sum of prescaled rows ----
__device__ __forceinline__ float2 gather64(const unsigned* __restrict__ src,
                                           int beg, int end, int lane) {
    float ax = 0.f, ay = 0.f;
    for (int e0 = beg; e0 < end; e0 += 32) {
        int e = e0 + lane;
        int cc = (e < end) ? g_ecol[e] : 0;
        int m = end - e0; if (m > 32) m = 32;
        int j = 0;
        for (; j + 8 <= m; j += 8) {
            int c0 = __shfl_sync(FULLM, cc, j + 0);
            int c1 = __shfl_sync(FULLM, cc, j + 1);
            int c2 = __shfl_sync(FULLM, cc, j + 2);
            int c3 = __shfl_sync(FULLM, cc, j + 3);
            int c4 = __shfl_sync(FULLM, cc, j + 4);
            int c5 = __shfl_sync(FULLM, cc, j + 5);
            int c6 = __shfl_sync(FULLM, cc, j + 6);
            int c7 = __shfl_sync(FULLM, cc, j + 7);
            unsigned v0 = __ldg(&src[(size_t)c0 * 32 + lane]);
            unsigned v1 = __ldg(&src[(size_t)c1 * 32 + lane]);
            unsigned v2 = __ldg(&src[(size_t)c2 * 32 + lane]);
            unsigned v3 = __ldg(&src[(size_t)c3 * 32 + lane]);
            unsigned v4 = __ldg(&src[(size_t)c4 * 32 + lane]);
            unsigned v5 = __ldg(&src[(size_t)c5 * 32 + lane]);
            unsigned v6 = __ldg(&src[(size_t)c6 * 32 + lane]);
            unsigned v7 = __ldg(&src[(size_t)c7 * 32 + lane]);
            float2 f;
            f = unpack2h(v0); ax += f.x; ay += f.y;
            f = unpack2h(v1); ax += f.x; ay += f.y;
            f = unpack2h(v2); ax += f.x; ay += f.y;
            f = unpack2h(v3); ax += f.x; ay += f.y;
            f = unpack2h(v4); ax += f.x; ay += f.y;
            f = unpack2h(v5); ax += f.x; ay += f.y;
            f = unpack2h(v6); ax += f.x; ay += f.y;
            f = unpack2h(v7); ax += f.x; ay += f.y;
        }
        for (; j < m; ++j) {
            int c0 = __shfl_sync(FULLM, cc, j);
            float2 f = unpack2h(__ldg(&src[(size_t)c0 * 32 + lane]));
            ax += f.x; ay += f.y;
        }
    }
    return make_float2(ax, ay);
}

// ---------------- propagate stages (64-dim). STAGE 2 writes final out --------
// STAGE 0: S = sum(yh[col]);  hA = dis^2 * S    (= dis * h1)
// STAGE 1: S = sum(hA[col]);  hB = dis^2 * S    (= dis * h2)
// STAGE 2: S = sum(hB[col]);  out = 0.25*(y + hA*inv + hB*inv + dis*S) + b
template <int STAGE>
__global__ void k_prop64(const float* __restrict__ bias, float* __restrict__ out) {
    const int gw   = (blockIdx.x * blockDim.x + threadIdx.x) >> 5;
    const int lane = threadIdx.x & 31;
    if (gw >= NN) return;
    const unsigned* __restrict__ src =
        (STAGE == 0) ? g_yh : (STAGE == 1) ? g_hA : g_hB;
    float2 a = gather64(src, g_rowptr[gw], g_rowptr[gw + 1], lane);
    const size_t o = (size_t)gw * 32 + lane;
    if (STAGE == 2) {
        float ds  = g_dis[gw];
        float inv = g_inv[gw];
        float2 yv = ((const float2*)g_yf)[o];
        float2 h1 = unpack2h(__ldg(&g_hA[o]));
        float2 h2 = unpack2h(__ldg(&g_hB[o]));
        float2 bv = __ldg((const float2*)bias + lane);
        float2 r;
        r.x = fmaf(0.25f, yv.x + h1.x * inv + h2.x * inv + ds * a.x, bv.x);
        r.y = fmaf(0.25f, yv.y + h1.y * inv + h2.y * inv + ds * a.y, bv.y);
        ((float2*)out)[o] = r;
    } else {
        float d2 = g_d2[gw];
        unsigned p = pack2h(d2 * a.x, d2 * a.y);
        if (STAGE == 1) g_hB[o] = p;
        else            g_hA[o] = p;
    }
}

// ---------------- launch -----------------------------------------------------
extern "C" void kernel_launch(void* const* d_in, const int* in_sizes, int n_in,
                              void* d_out, int out_size) {
    const float* x   = (const float*)d_in[0];   // [NN, HID]
    const int*   ei  = (const int*)d_in[1];     // [2, NE] int32
    const float* W   = (const float*)d_in[2];   // [NOUT, HID]
    const float* b   = (const float*)d_in[3];   // [NOUT]
    float*       out = (float*)d_out;           // [NN, NOUT]

    const int TB = 256;
    const int gE = (NE + TB - 1) / TB;
    const int gP = (NN * 32 + TB - 1) / TB;   // warp per node
    const int gG = (NN + 127) / 128;

    // g_cnt is zero on entry (zero-init on load; k_scan3 re-zeroes each launch)
    k_count<<<gE, TB>>>(ei);
    k_scan1<<<NB_SCAN, SCAN_B>>>();
    k_scan2<<<1, 128>>>();
    k_scan3<<<NB_SCAN, SCAN_B>>>();           // rowptr/cursor/dis/d2/inv + cnt=0
    k_scatter<<<gE, TB>>>(ei);
    k_gemm_y<<<gG, 128>>>(x, W);              // y fp32 + ŷ=dis*y half

    k_prop64<0><<<gP, TB>>>(b, out);          // ŷ  -> hA
    k_prop64<1><<<gP, TB>>>(b, out);          // hA -> hB
    k_prop64<2><<<gP, TB>>>(b, out);          // hB -> out (mean+bias fused)

    (void)in_sizes; (void)n_in; (void)out_size;
}